// round 12
// baseline (speedup 1.0000x reference)
#include <cuda_runtime.h>
#include <cuda_fp16.h>
#include <math.h>
#include <stdint.h>

#define D_MODEL 1024
#define T_TOT   2052
#define MPAD    2176   // 17*128
#define L_SEQ   2048
#define NP      4
#define NHEADS  16
#define HD      64
#define WIN     128

// ---------------- scratch (device globals: allocation-free) ----------------
__device__ __half g_QKVh[3][T_TOT * D_MODEL]; // pre-conv Q,K,V (fp16, GEMM out)
__device__ __half g_Qh[T_TOT * D_MODEL];      // post conv+silu+norm, fp16
__device__ __half g_Kh[T_TOT * D_MODEL];
__device__ __half g_Vh[T_TOT * D_MODEL];
__device__ __half g_xp_h[MPAD * D_MODEL];     // input (pm;x) fp16
__device__ __half g_w_h[4][D_MODEL * D_MODEL];// weights fp16
__device__ __half g_at_h[L_SEQ * D_MODEL];    // attention output fp16

// ---------------- helpers ----------------
__device__ __forceinline__ uint32_t smem_u32(const void* p) {
    uint32_t a;
    asm("{ .reg .u64 t; cvta.to.shared.u64 t, %1; cvt.u32.u64 %0, t; }" : "=r"(a) : "l"(p));
    return a;
}

#define LDSM4(R0, R1, R2, R3, ADDR) \
    asm volatile("ldmatrix.sync.aligned.m8n8.x4.shared.b16 {%0,%1,%2,%3}, [%4];" \
                 : "=r"(R0), "=r"(R1), "=r"(R2), "=r"(R3) : "r"(ADDR))

#define LDSM2T(R0, R1, ADDR) \
    asm volatile("ldmatrix.sync.aligned.m8n8.x2.trans.shared.b16 {%0,%1}, [%2];" \
                 : "=r"(R0), "=r"(R1) : "r"(ADDR))

#define MMA16816(D, A0, A1, A2, A3, B0, B1) \
    asm volatile("mma.sync.aligned.m16n8k16.row.col.f32.f16.f16.f32 " \
                 "{%0,%1,%2,%3}, {%4,%5,%6,%7}, {%8,%9}, {%0,%1,%2,%3};" \
                 : "+f"((D)[0]), "+f"((D)[1]), "+f"((D)[2]), "+f"((D)[3]) \
                 : "r"(A0), "r"(A1), "r"(A2), "r"(A3), "r"(B0), "r"(B1))

#define CP_ASYNC16(S, G) \
    asm volatile("cp.async.cg.shared.global [%0], [%1], 16;" :: "r"(S), "l"(G))
#define CP_COMMIT()  asm volatile("cp.async.commit_group;" ::: "memory")

__device__ __forceinline__ uint32_t pack2h(float a, float b) {
    __half2 h = __floats2half2_rn(a, b);
    return *(uint32_t*)&h;
}
__device__ __forceinline__ uint2 cvt4h(float4 v) {
    uint2 r;
    r.x = pack2h(v.x, v.y);
    r.y = pack2h(v.z, v.w);
    return r;
}

// fused converts: blocks [0,4096) = weights, [4096, 4096+2176) = xp
__global__ void __launch_bounds__(256) convert_all_kernel(const float* __restrict__ pm,
                                                          const float* __restrict__ x,
                                                          const float* __restrict__ Wq,
                                                          const float* __restrict__ Wk,
                                                          const float* __restrict__ Wv,
                                                          const float* __restrict__ Wo)
{
    int bx = blockIdx.x;
    if (bx < 4096) {
        int w = bx >> 10;
        const float* src = (w == 0) ? Wq : (w == 1) ? Wk : (w == 2) ? Wv : Wo;
        int i = ((bx & 1023) * 256 + threadIdx.x) * 4;
        *(uint2*)(&g_w_h[w][i]) = cvt4h(*(const float4*)(src + i));
    } else {
        int i = ((bx - 4096) * 256 + threadIdx.x) * 4;
        int row = i >> 10, col = i & 1023;
        float4 v = make_float4(0.f, 0.f, 0.f, 0.f);
        if (row < NP)          v = *(const float4*)(pm + row * D_MODEL + col);
        else if (row < T_TOT)  v = *(const float4*)(x + (size_t)(row - NP) * D_MODEL + col);
        *(uint2*)(&g_xp_h[i]) = cvt4h(v);
    }
}

// ---------------- mma.sync GEMM: C[128,BN]-tile = A @ B^T ----------------
// 4 warps (2 in M x 2 in N), warp tile 64 x BN/2. NSTAGE-deep cp.async pipeline.
#define QKV_SMEM (2 * (16384 + 128 * 128))   // BN=128, 2 stages = 64KB
#define OUT_SMEM (3 * (16384 + 64 * 128))    // BN=64, 3 stages = 72KB

template <int BN, int NSTAGE, typename OutT>
__device__ __forceinline__ void gemm_body(const __half* __restrict__ Ah,
                                          const __half* __restrict__ Bh,
                                          OutT* __restrict__ C, int Mrows)
{
    constexpr int STAGE_BYTES = 16384 + BN * 128;
    constexpr int NWT = (BN / 2) / 8;    // 8-col n-tiles per warp
    constexpr int NPL = (BN / 2) / 16;   // 16-col ldsm groups per warp
    extern __shared__ __align__(1024) char sm[];
    uint32_t sbase = smem_u32(sm);
    int tid = threadIdx.x;
    int lane = tid & 31, wid = tid >> 5;
    int bm = blockIdx.y, bn = blockIdx.x;

    const __half* srcA = Ah + (size_t)bm * 128 * D_MODEL;
    const __half* srcB = Bh + (size_t)bn * BN * D_MODEL;

    auto issue_chunk = [&](int kc, int s) {
        uint32_t stage = sbase + s * STAGE_BYTES;
#pragma unroll
        for (int it = 0; it < (128 + BN) / 16; it++) {
            int g = it * 128 + tid;
            int mat = g >= 1024;
            int r = mat ? ((g - 1024) >> 3) : (g >> 3);
            int c = g & 7;
            const __half* gp = (mat ? srcB : srcA) + (size_t)r * D_MODEL + kc * 64 + c * 8;
            uint32_t so = stage + mat * 16384 + r * 128 + ((c * 16) ^ ((r & 7) << 4));
            CP_ASYNC16(so, gp);
        }
    };

    int m_base = (wid & 1) * 64;
    int n_base = (wid >> 1) * (BN / 2);

    int arow0 = m_base + (lane & 15);
    int ak2 = ((lane >> 4) * 8) * 2;
    int brow0 = n_base + (lane & 7) + ((lane >> 4) << 3);
    int bk2 = (((lane >> 3) & 1) * 8) * 2;

    uint32_t aoffs[4], asw[4], boffs[NPL], bsw[NPL];
#pragma unroll
    for (int mi = 0; mi < 4; mi++) {
        int r = arow0 + mi * 16;
        aoffs[mi] = r * 128; asw[mi] = (r & 7) << 4;
    }
#pragma unroll
    for (int p = 0; p < NPL; p++) {
        int r = brow0 + p * 16;
        boffs[p] = r * 128; bsw[p] = (r & 7) << 4;
    }

    float acc[4][NWT][4];
#pragma unroll
    for (int mi = 0; mi < 4; mi++)
#pragma unroll
        for (int n = 0; n < NWT; n++)
#pragma unroll
            for (int j = 0; j < 4; j++) acc[mi][n][j] = 0.f;

#pragma unroll
    for (int s = 0; s < NSTAGE; s++) { issue_chunk(s, s); CP_COMMIT(); }

    for (int kc = 0; kc < 16; kc++) {
        asm volatile("cp.async.wait_group %0;" :: "n"(NSTAGE - 1) : "memory");
        __syncthreads();
        uint32_t stage = sbase + (kc % NSTAGE) * STAGE_BYTES;
        uint32_t AH = stage, BH = stage + 16384;
#pragma unroll
        for (int ks = 0; ks < 4; ks++) {
            uint32_t kb2 = ks * 32;
            uint32_t ah[4][4];
#pragma unroll
            for (int mi = 0; mi < 4; mi++)
                LDSM4(ah[mi][0], ah[mi][1], ah[mi][2], ah[mi][3],
                      AH + aoffs[mi] + ((kb2 + ak2) ^ asw[mi]));
#pragma unroll
            for (int p = 0; p < NPL; p++) {
                uint32_t bh[4];
                LDSM4(bh[0], bh[1], bh[2], bh[3], BH + boffs[p] + ((kb2 + bk2) ^ bsw[p]));
#pragma unroll
                for (int mi = 0; mi < 4; mi++) {
                    MMA16816(acc[mi][2 * p],     ah[mi][0], ah[mi][1], ah[mi][2], ah[mi][3], bh[0], bh[1]);
                    MMA16816(acc[mi][2 * p + 1], ah[mi][0], ah[mi][1], ah[mi][2], ah[mi][3], bh[2], bh[3]);
                }
            }
        }
        __syncthreads();
        int cN = kc + NSTAGE;
        if (cN < 16) issue_chunk(cN, cN % NSTAGE);
        CP_COMMIT();
    }

    int crow = lane >> 2;
    int ccol = (lane & 3) * 2;
#pragma unroll
    for (int mi = 0; mi < 4; mi++) {
#pragma unroll
        for (int n = 0; n < NWT; n++) {
            int row0 = bm * 128 + m_base + mi * 16 + crow;
            int col = bn * BN + n_base + n * 8 + ccol;
            if (row0 < Mrows) {
                if constexpr (sizeof(OutT) == 2)
                    *(uint32_t*)((__half*)C + (size_t)row0 * D_MODEL + col) = pack2h(acc[mi][n][0], acc[mi][n][1]);
                else
                    *(float2*)((float*)C + (size_t)row0 * D_MODEL + col) = make_float2(acc[mi][n][0], acc[mi][n][1]);
            }
            int row1 = row0 + 8;
            if (row1 < Mrows) {
                if constexpr (sizeof(OutT) == 2)
                    *(uint32_t*)((__half*)C + (size_t)row1 * D_MODEL + col) = pack2h(acc[mi][n][2], acc[mi][n][3]);
                else
                    *(float2*)((float*)C + (size_t)row1 * D_MODEL + col) = make_float2(acc[mi][n][2], acc[mi][n][3]);
            }
        }
    }
}

__global__ void __launch_bounds__(128, 3) gemm_qkv_tc(void)
{
    int z = blockIdx.z;
    gemm_body<128, 2, __half>(g_xp_h, g_w_h[z], g_QKVh[z], T_TOT);
}
__global__ void __launch_bounds__(128, 3) gemm_out_tc(float* __restrict__ out)
{
    gemm_body<64, 3, float>(g_at_h, g_w_h[3], out, L_SEQ);
}

// ---------------- fused conv(k=3) + bias + SiLU + (L2 norm) -> fp16 ----
__global__ void __launch_bounds__(256, 4) conv_silu_norm_kernel(const float* __restrict__ qw,
                                                                const float* __restrict__ qb,
                                                                const float* __restrict__ kw,
                                                                const float* __restrict__ kb,
                                                                const float* __restrict__ vw,
                                                                const float* __restrict__ vb)
{
    int m = blockIdx.y;
    int t0 = blockIdx.x * 4;
    const float* w = (m == 0) ? qw : (m == 1) ? kw : vw;
    const float* b = (m == 0) ? qb : (m == 1) ? kb : vb;
    const __half* X = g_QKVh[m];
    int tid = threadIdx.x;
    int d4 = tid * 4;

    float w0[4], w1[4], w2[4], bb[4];
#pragma unroll
    for (int j = 0; j < 4; j++) {
        w0[j] = w[(d4 + j) * 3 + 0];
        w1[j] = w[(d4 + j) * 3 + 1];
        w2[j] = w[(d4 + j) * 3 + 2];
        bb[j] = b[d4 + j];
    }

    float xr[6][4];
#pragma unroll
    for (int i = 0; i < 6; i++) {
        int t = t0 - 2 + i;
        if (t >= 0) {
            uint2 hv = *(const uint2*)(X + (size_t)t * D_MODEL + d4);
            __half2 h01 = *(__half2*)&hv.x;
            __half2 h23 = *(__half2*)&hv.y;
            xr[i][0] = __low2float(h01); xr[i][1] = __high2float(h01);
            xr[i][2] = __low2float(h23); xr[i][3] = __high2float(h23);
        } else {
            xr[i][0] = xr[i][1] = xr[i][2] = xr[i][3] = 0.f;
        }
    }

    float y[4][4];
    float ss[4] = {0.f, 0.f, 0.f, 0.f};
#pragma unroll
    for (int tt = 0; tt < 4; tt++) {
#pragma unroll
        for (int j = 0; j < 4; j++) {
            float z = w0[j] * xr[tt][j] + w1[j] * xr[tt + 1][j] + w2[j] * xr[tt + 2][j] + bb[j];
            float yv = z / (1.f + __expf(-z));
            y[tt][j] = yv;
            ss[tt] += yv * yv;
        }
    }

    __shared__ float red[4][8];
#pragma unroll
    for (int o = 16; o > 0; o >>= 1) {
#pragma unroll
        for (int tt = 0; tt < 4; tt++) ss[tt] += __shfl_xor_sync(0xffffffffu, ss[tt], o);
    }
    if ((tid & 31) == 0) {
#pragma unroll
        for (int tt = 0; tt < 4; tt++) red[tt][tid >> 5] = ss[tt];
    }
    __syncthreads();
    float inv[4];
#pragma unroll
    for (int tt = 0; tt < 4; tt++) {
        float total = red[tt][0] + red[tt][1] + red[tt][2] + red[tt][3]
                    + red[tt][4] + red[tt][5] + red[tt][6] + red[tt][7];
        inv[tt] = (m < 2) ? 1.f / fmaxf(sqrtf(total), 1e-12f) : 1.f;
    }

    __half* dst = (m == 0) ? g_Qh : (m == 1) ? g_Kh : g_Vh;
#pragma unroll
    for (int tt = 0; tt < 4; tt++) {
        uint2 hv = cvt4h(make_float4(y[tt][0] * inv[tt], y[tt][1] * inv[tt],
                                     y[tt][2] * inv[tt], y[tt][3] * inv[tt]));
        *(uint2*)(dst + (size_t)(t0 + tt) * D_MODEL + d4) = hv;
    }
}

// ---------------- tensor-core attention (AQ=128, 8 warps, 2 CTAs/SM) ------
// Slots: 0-3 persistent, 4..258 window keys [q0-127, q0+127], padded to 272.
// Warp w owns queries 16w..16w+15; needs blocks w..w+9 + block 0.
// Interior blocks w+2..w+7 are provably fully-valid when tile>=1 -> mask-free.
#define ASLOT 272
#define AQ    128
#define AT_QO 0
#define AT_KO 16384
#define AT_VH (16384 + 34816)
#define ATTN_SMEM (16384 + 2 * 34816)

__global__ void __launch_bounds__(256, 2) attn_tc_kernel()
{
    extern __shared__ __align__(1024) char smc[];
    uint32_t sb = smem_u32(smc);
    int tid = threadIdx.x;
    int lane = tid & 31, w = tid >> 5;
    int h = blockIdx.x, tile = blockIdx.y;
    int q0 = NP + tile * AQ;
    int kmin = q0 - (WIN - 1);
    int hoff = h * HD;

    // ---- stage Q (128x64) ----
    for (int i = tid; i < 1024; i += 256) {
        int r = i >> 3, c = i & 7;
        uint4 v = *(const uint4*)(g_Qh + (size_t)(q0 + r) * D_MODEL + hoff + c * 8);
        *(uint4*)(smc + AT_QO + r * 128 + ((c * 16) ^ ((r & 7) << 4))) = v;
    }
    // ---- stage K, V (clamp only window slots) ----
    for (int i = tid; i < ASLOT * 8; i += 256) {
        int s = i >> 3, c = i & 7;
        int key = (s < 4) ? s : min(max(kmin + s - 4, NP), T_TOT - 1);
        size_t gidx = (size_t)key * D_MODEL + hoff + c * 8;
        uint32_t off = s * 128 + ((c * 16) ^ ((s & 7) << 4));
        *(uint4*)(smc + AT_KO + off) = *(const uint4*)(g_Kh + gidx);
        *(uint4*)(smc + AT_VH + off) = *(const uint4*)(g_Vh + gidx);
    }
    __syncthreads();

    // ---- per-warp Q fragments (rows 16w..16w+15, k=64) ----
    uint32_t qf[4][4];
    {
        int ar = 16 * w + (lane & 15);
        uint32_t base = sb + AT_QO + ar * 128;
        uint32_t sw = (ar & 7) << 4;
        int ak = (lane >> 4) * 16;
#pragma unroll
        for (int ks = 0; ks < 4; ks++)
            LDSM4(qf[ks][0], qf[ks][1], qf[ks][2], qf[ks][3],
                  base + ((ks * 32 + ak) ^ sw));
    }

    int qrow0 = q0 + 16 * w + (lane >> 2);
    int ccol = (lane & 3) * 2;

    float o[8][4];
#pragma unroll
    for (int n = 0; n < 8; n++)
#pragma unroll
        for (int j = 0; j < 4; j++) o[n][j] = 0.f;
    float l0 = 0.f, l1 = 0.f;

    int krel = (lane & 7) + ((lane >> 4) << 3);
    int kb2 = ((lane >> 3) & 1) * 16;
    int vrel = lane & 15;

    auto process_block = [&](int bi, bool masked) {
        int sbase_slot = bi * 16;
        float s0[4] = {0.f, 0.f, 0.f, 0.f}, s1[4] = {0.f, 0.f, 0.f, 0.f};
        {
            int r = sbase_slot + krel;
            uint32_t base = sb + AT_KO + r * 128;
            uint32_t sw = (r & 7) << 4;
#pragma unroll
            for (int ks = 0; ks < 4; ks++) {
                uint32_t b0, b1, b2, b3;
                LDSM4(b0, b1, b2, b3, base + ((ks * 32 + kb2) ^ sw));
                MMA16816(s0, qf[ks][0], qf[ks][1], qf[ks][2], qf[ks][3], b0, b1);
                MMA16816(s1, qf[ks][0], qf[ks][1], qf[ks][2], qf[ks][3], b2, b3);
            }
        }
        float p[8];
        if (masked) {
#pragma unroll
            for (int e = 0; e < 8; e++) {
                int tilen = e >> 2;
                int j = e & 3;
                int slot = sbase_slot + tilen * 8 + ccol + (j & 1);
                int qr = (j < 2) ? qrow0 : qrow0 + 8;
                float sc = tilen ? s1[j] : s0[j];
                int k = slot < 4 ? slot : kmin + slot - 4;
                bool valid = (slot < 4) | ((k >= NP) & (k <= qr) & (k > qr - WIN));
                p[e] = valid ? __expf(sc * 0.125f) : 0.f;
            }
        } else {
#pragma unroll
            for (int e = 0; e < 8; e++) {
                float sc = (e >> 2) ? s1[e & 3] : s0[e & 3];
                p[e] = __expf(sc * 0.125f);
            }
        }
        l0 += p[0] + p[1] + p[4] + p[5];
        l1 += p[2] + p[3] + p[6] + p[7];
        uint32_t a0 = pack2h(p[0], p[1]);
        uint32_t a1 = pack2h(p[2], p[3]);
        uint32_t a2 = pack2h(p[4], p[5]);
        uint32_t a3 = pack2h(p[6], p[7]);
        {
            int r = sbase_slot + vrel;
            uint32_t swv = (r & 7) << 4;
            uint32_t bh = sb + AT_VH + r * 128;
#pragma unroll
            for (int nt = 0; nt < 8; nt++) {
                uint32_t v0, v1;
                LDSM2T(v0, v1, bh + ((nt * 16) ^ swv));
                MMA16816(o[nt], a0, a1, a2, a3, v0, v1);
            }
        }
    };

    bool safe = (tile >= 1);   // kmin >= NP: interior blocks need no mask
    process_block(0, true);
    if (w >= 1) process_block(w, true);
    process_block(w + 1, true);
    for (int bi = w + 2; bi <= w + 7; bi++) process_block(bi, !safe);
    process_block(w + 8, true);
    process_block(w + 9, true);

    l0 += __shfl_xor_sync(0xffffffffu, l0, 1);
    l0 += __shfl_xor_sync(0xffffffffu, l0, 2);
    l1 += __shfl_xor_sync(0xffffffffu, l1, 1);
    l1 += __shfl_xor_sync(0xffffffffu, l1, 2);
    float inv0 = 1.f / l0, inv1 = 1.f / l1;

    size_t r0 = (size_t)(qrow0 - NP) * D_MODEL + hoff + ccol;
    size_t r1 = r0 + 8 * D_MODEL;
#pragma unroll
    for (int nt = 0; nt < 8; nt++) {
        *(uint32_t*)(&g_at_h[r0 + nt * 8]) = pack2h(o[nt][0] * inv0, o[nt][1] * inv0);
        *(uint32_t*)(&g_at_h[r1 + nt * 8]) = pack2h(o[nt][2] * inv1, o[nt][3] * inv1);
    }
}

// ---------------- launch ----------------
extern "C" void kernel_launch(void* const* d_in, const int* in_sizes, int n_in,
                              void* d_out, int out_size)
{
    (void)in_sizes; (void)n_in; (void)out_size;
    const float* x  = (const float*)d_in[0];
    const float* pm = (const float*)d_in[1];
    const float* Wq = (const float*)d_in[2];
    const float* Wk = (const float*)d_in[3];
    const float* Wv = (const float*)d_in[4];
    const float* Wo = (const float*)d_in[5];
    const float* qw = (const float*)d_in[6];
    const float* qb = (const float*)d_in[7];
    const float* kw = (const float*)d_in[8];
    const float* kb = (const float*)d_in[9];
    const float* vw = (const float*)d_in[10];
    const float* vb = (const float*)d_in[11];
    float* out = (float*)d_out;

    cudaFuncSetAttribute(attn_tc_kernel, cudaFuncAttributeMaxDynamicSharedMemorySize, ATTN_SMEM);
    cudaFuncSetAttribute(gemm_qkv_tc, cudaFuncAttributeMaxDynamicSharedMemorySize, QKV_SMEM);
    cudaFuncSetAttribute(gemm_out_tc, cudaFuncAttributeMaxDynamicSharedMemorySize, OUT_SMEM);

    convert_all_kernel<<<4096 + MPAD, 256>>>(pm, x, Wq, Wk, Wv, Wo);

    gemm_qkv_tc<<<dim3(8, 17, 3), 128, QKV_SMEM>>>();

    conv_silu_norm_kernel<<<dim3(T_TOT / 4, 3), 256>>>(qw, qb, kw, kb, vw, vb);

    attn_tc_kernel<<<dim3(NHEADS, L_SEQ / AQ), 256, ATTN_SMEM>>>();

    gemm_out_tc<<<dim3(16, 16), 128, OUT_SMEM>>>(out);
}

// round 14
// speedup vs baseline: 1.0245x; 1.0245x over previous
#include <cuda_runtime.h>
#include <cuda_fp16.h>
#include <math.h>
#include <stdint.h>

#define D_MODEL 1024
#define T_TOT   2052
#define MPAD    2176   // 17*128
#define L_SEQ   2048
#define NP      4
#define NHEADS  16
#define HD      64
#define WIN     128

// ---------------- scratch (device globals: allocation-free) ----------------
__device__ __half g_QKVh[3][T_TOT * D_MODEL]; // pre-conv Q,K,V (fp16, GEMM out)
__device__ __half g_Qh[T_TOT * D_MODEL];      // post conv+silu+norm, fp16
__device__ __half g_Kh[T_TOT * D_MODEL];
__device__ __half g_Vh[T_TOT * D_MODEL];
__device__ __half g_xp_h[MPAD * D_MODEL];     // input (pm;x) fp16
__device__ __half g_w_h[4][D_MODEL * D_MODEL];// weights fp16
__device__ __half g_at_h[L_SEQ * D_MODEL];    // attention output fp16

// ---------------- helpers ----------------
__device__ __forceinline__ uint32_t smem_u32(const void* p) {
    uint32_t a;
    asm("{ .reg .u64 t; cvta.to.shared.u64 t, %1; cvt.u32.u64 %0, t; }" : "=r"(a) : "l"(p));
    return a;
}

#define LDSM4(R0, R1, R2, R3, ADDR) \
    asm volatile("ldmatrix.sync.aligned.m8n8.x4.shared.b16 {%0,%1,%2,%3}, [%4];" \
                 : "=r"(R0), "=r"(R1), "=r"(R2), "=r"(R3) : "r"(ADDR))

#define LDSM2T(R0, R1, ADDR) \
    asm volatile("ldmatrix.sync.aligned.m8n8.x2.trans.shared.b16 {%0,%1}, [%2];" \
                 : "=r"(R0), "=r"(R1) : "r"(ADDR))

#define MMA16816(D, A0, A1, A2, A3, B0, B1) \
    asm volatile("mma.sync.aligned.m16n8k16.row.col.f32.f16.f16.f32 " \
                 "{%0,%1,%2,%3}, {%4,%5,%6,%7}, {%8,%9}, {%0,%1,%2,%3};" \
                 : "+f"((D)[0]), "+f"((D)[1]), "+f"((D)[2]), "+f"((D)[3]) \
                 : "r"(A0), "r"(A1), "r"(A2), "r"(A3), "r"(B0), "r"(B1))

#define CP_ASYNC16(S, G) \
    asm volatile("cp.async.cg.shared.global [%0], [%1], 16;" :: "r"(S), "l"(G))
#define CP_COMMIT()  asm volatile("cp.async.commit_group;" ::: "memory")

__device__ __forceinline__ uint32_t pack2h(float a, float b) {
    __half2 h = __floats2half2_rn(a, b);
    return *(uint32_t*)&h;
}
__device__ __forceinline__ uint2 cvt4h(float4 v) {
    uint2 r;
    r.x = pack2h(v.x, v.y);
    r.y = pack2h(v.z, v.w);
    return r;
}

// fused converts: blocks [0,4096) = weights, [4096, 4096+2176) = xp
__global__ void __launch_bounds__(256) convert_all_kernel(const float* __restrict__ pm,
                                                          const float* __restrict__ x,
                                                          const float* __restrict__ Wq,
                                                          const float* __restrict__ Wk,
                                                          const float* __restrict__ Wv,
                                                          const float* __restrict__ Wo)
{
    int bx = blockIdx.x;
    if (bx < 4096) {
        int w = bx >> 10;
        const float* src = (w == 0) ? Wq : (w == 1) ? Wk : (w == 2) ? Wv : Wo;
        int i = ((bx & 1023) * 256 + threadIdx.x) * 4;
        *(uint2*)(&g_w_h[w][i]) = cvt4h(*(const float4*)(src + i));
    } else {
        int i = ((bx - 4096) * 256 + threadIdx.x) * 4;
        int row = i >> 10, col = i & 1023;
        float4 v = make_float4(0.f, 0.f, 0.f, 0.f);
        if (row < NP)          v = *(const float4*)(pm + row * D_MODEL + col);
        else if (row < T_TOT)  v = *(const float4*)(x + (size_t)(row - NP) * D_MODEL + col);
        *(uint2*)(&g_xp_h[i]) = cvt4h(v);
    }
}

// ---------------- mma.sync GEMM: C[128,128]-tile = A @ B^T ----------------
// 4 warps (2x2), warp tile 64x64. NSTAGE-deep cp.async pipeline; stage = 32KB.
#define QKV_SMEM (2 * 32768)   // 2 stages, 3 CTAs/SM (single wave for 408 CTAs)
#define OUT_SMEM (3 * 32768)   // 3 stages, 2 CTAs/SM (R11 winner config)

template <int NSTAGE, typename OutT>
__device__ __forceinline__ void gemm128_body(const __half* __restrict__ Ah,
                                             const __half* __restrict__ Bh,
                                             OutT* __restrict__ C, int Mrows)
{
    extern __shared__ __align__(1024) char sm[];
    uint32_t sbase = smem_u32(sm);
    int tid = threadIdx.x;
    int lane = tid & 31, wid = tid >> 5;
    int bm = blockIdx.y, bn = blockIdx.x;

    const __half* srcA = Ah + (size_t)bm * 128 * D_MODEL;
    const __half* srcB = Bh + (size_t)bn * 128 * D_MODEL;

    auto issue_chunk = [&](int kc, int s) {
        uint32_t stage = sbase + s * 32768;
#pragma unroll
        for (int it = 0; it < 16; it++) {
            int g = it * 128 + tid;
            int mat = g >> 10;
            int r = (g & 1023) >> 3;
            int c = g & 7;
            const __half* gp = (mat ? srcB : srcA) + (size_t)r * D_MODEL + kc * 64 + c * 8;
            uint32_t so = stage + mat * 16384 + r * 128 + ((c * 16) ^ ((r & 7) << 4));
            CP_ASYNC16(so, gp);
        }
    };

    int m_base = (wid & 1) * 64;
    int n_base = (wid >> 1) * 64;

    int arow0 = m_base + (lane & 15);
    int ak2 = ((lane >> 4) * 8) * 2;
    int brow0 = n_base + (lane & 7) + ((lane >> 4) << 3);
    int bk2 = (((lane >> 3) & 1) * 8) * 2;

    uint32_t aoffs[4], asw[4], boffs[4], bsw[4];
#pragma unroll
    for (int mi = 0; mi < 4; mi++) {
        int r = arow0 + mi * 16;
        aoffs[mi] = r * 128; asw[mi] = (r & 7) << 4;
    }
#pragma unroll
    for (int p = 0; p < 4; p++) {
        int r = brow0 + p * 16;
        boffs[p] = r * 128; bsw[p] = (r & 7) << 4;
    }

    float acc[4][8][4];
#pragma unroll
    for (int mi = 0; mi < 4; mi++)
#pragma unroll
        for (int n = 0; n < 8; n++)
#pragma unroll
            for (int j = 0; j < 4; j++) acc[mi][n][j] = 0.f;

#pragma unroll
    for (int s = 0; s < NSTAGE; s++) { issue_chunk(s, s); CP_COMMIT(); }

    for (int kc = 0; kc < 16; kc++) {
        asm volatile("cp.async.wait_group %0;" :: "n"(NSTAGE - 1) : "memory");
        __syncthreads();
        uint32_t stage = sbase + (kc % NSTAGE) * 32768;
        uint32_t AH = stage, BH = stage + 16384;
#pragma unroll
        for (int ks = 0; ks < 4; ks++) {
            uint32_t kb2 = ks * 32;
            uint32_t ah[4][4];
#pragma unroll
            for (int mi = 0; mi < 4; mi++)
                LDSM4(ah[mi][0], ah[mi][1], ah[mi][2], ah[mi][3],
                      AH + aoffs[mi] + ((kb2 + ak2) ^ asw[mi]));
#pragma unroll
            for (int p = 0; p < 4; p++) {
                uint32_t bh[4];
                LDSM4(bh[0], bh[1], bh[2], bh[3], BH + boffs[p] + ((kb2 + bk2) ^ bsw[p]));
#pragma unroll
                for (int mi = 0; mi < 4; mi++) {
                    MMA16816(acc[mi][2 * p],     ah[mi][0], ah[mi][1], ah[mi][2], ah[mi][3], bh[0], bh[1]);
                    MMA16816(acc[mi][2 * p + 1], ah[mi][0], ah[mi][1], ah[mi][2], ah[mi][3], bh[2], bh[3]);
                }
            }
        }
        __syncthreads();
        int cN = kc + NSTAGE;
        if (cN < 16) issue_chunk(cN, cN % NSTAGE);
        CP_COMMIT();
    }

    int crow = lane >> 2;
    int ccol = (lane & 3) * 2;
#pragma unroll
    for (int mi = 0; mi < 4; mi++) {
#pragma unroll
        for (int n = 0; n < 8; n++) {
            int row0 = bm * 128 + m_base + mi * 16 + crow;
            int col = bn * 128 + n_base + n * 8 + ccol;
            if (row0 < Mrows) {
                if constexpr (sizeof(OutT) == 2)
                    *(uint32_t*)((__half*)C + (size_t)row0 * D_MODEL + col) = pack2h(acc[mi][n][0], acc[mi][n][1]);
                else
                    *(float2*)((float*)C + (size_t)row0 * D_MODEL + col) = make_float2(acc[mi][n][0], acc[mi][n][1]);
            }
            int row1 = row0 + 8;
            if (row1 < Mrows) {
                if constexpr (sizeof(OutT) == 2)
                    *(uint32_t*)((__half*)C + (size_t)row1 * D_MODEL + col) = pack2h(acc[mi][n][2], acc[mi][n][3]);
                else
                    *(float2*)((float*)C + (size_t)row1 * D_MODEL + col) = make_float2(acc[mi][n][2], acc[mi][n][3]);
            }
        }
    }
}

__global__ void __launch_bounds__(128, 3) gemm_qkv_tc(void)
{
    int z = blockIdx.z;
    gemm128_body<2, __half>(g_xp_h, g_w_h[z], g_QKVh[z], T_TOT);
}
__global__ void __launch_bounds__(128, 2) gemm_out_tc(float* __restrict__ out)
{
    gemm128_body<3, float>(g_at_h, g_w_h[3], out, L_SEQ);
}

// ---------------- fused conv(k=3) + bias + SiLU + (L2 norm) -> fp16 ----
__global__ void __launch_bounds__(256) conv_silu_norm_kernel(const float* __restrict__ qw,
                                                             const float* __restrict__ qb,
                                                             const float* __restrict__ kw,
                                                             const float* __restrict__ kb,
                                                             const float* __restrict__ vw,
                                                             const float* __restrict__ vb)
{
    int m = blockIdx.y;
    int t0 = blockIdx.x * 4;
    const float* w = (m == 0) ? qw : (m == 1) ? kw : vw;
    const float* b = (m == 0) ? qb : (m == 1) ? kb : vb;
    const __half* X = g_QKVh[m];
    int tid = threadIdx.x;
    int d4 = tid * 4;

    float w0[4], w1[4], w2[4], bb[4];
#pragma unroll
    for (int j = 0; j < 4; j++) {
        w0[j] = w[(d4 + j) * 3 + 0];
        w1[j] = w[(d4 + j) * 3 + 1];
        w2[j] = w[(d4 + j) * 3 + 2];
        bb[j] = b[d4 + j];
    }

    float xr[6][4];
#pragma unroll
    for (int i = 0; i < 6; i++) {
        int t = t0 - 2 + i;
        if (t >= 0) {
            uint2 hv = *(const uint2*)(X + (size_t)t * D_MODEL + d4);
            __half2 h01 = *(__half2*)&hv.x;
            __half2 h23 = *(__half2*)&hv.y;
            xr[i][0] = __low2float(h01); xr[i][1] = __high2float(h01);
            xr[i][2] = __low2float(h23); xr[i][3] = __high2float(h23);
        } else {
            xr[i][0] = xr[i][1] = xr[i][2] = xr[i][3] = 0.f;
        }
    }

    float y[4][4];
    float ss[4] = {0.f, 0.f, 0.f, 0.f};
#pragma unroll
    for (int tt = 0; tt < 4; tt++) {
#pragma unroll
        for (int j = 0; j < 4; j++) {
            float z = w0[j] * xr[tt][j] + w1[j] * xr[tt + 1][j] + w2[j] * xr[tt + 2][j] + bb[j];
            float yv = z / (1.f + __expf(-z));
            y[tt][j] = yv;
            ss[tt] += yv * yv;
        }
    }

    __shared__ float red[4][8];
#pragma unroll
    for (int o = 16; o > 0; o >>= 1) {
#pragma unroll
        for (int tt = 0; tt < 4; tt++) ss[tt] += __shfl_xor_sync(0xffffffffu, ss[tt], o);
    }
    if ((tid & 31) == 0) {
#pragma unroll
        for (int tt = 0; tt < 4; tt++) red[tt][tid >> 5] = ss[tt];
    }
    __syncthreads();
    float inv[4];
#pragma unroll
    for (int tt = 0; tt < 4; tt++) {
        float total = red[tt][0] + red[tt][1] + red[tt][2] + red[tt][3]
                    + red[tt][4] + red[tt][5] + red[tt][6] + red[tt][7];
        inv[tt] = (m < 2) ? 1.f / fmaxf(sqrtf(total), 1e-12f) : 1.f;
    }

    __half* dst = (m == 0) ? g_Qh : (m == 1) ? g_Kh : g_Vh;
#pragma unroll
    for (int tt = 0; tt < 4; tt++) {
        uint2 hv = cvt4h(make_float4(y[tt][0] * inv[tt], y[tt][1] * inv[tt],
                                     y[tt][2] * inv[tt], y[tt][3] * inv[tt]));
        *(uint2*)(dst + (size_t)(t0 + tt) * D_MODEL + d4) = hv;
    }
}

// ---------------- tensor-core attention (AQ=128, 8 warps, 2 CTAs/SM) ------
// Slots: 0-3 persistent, 4..258 window keys [q0-127, q0+127], padded to 272.
// Warp w owns queries 16w..16w+15; needs blocks w..w+9 + block 0.
// Interior blocks w+2..w+7 are provably fully-valid when tile>=1 -> mask-free.
#define ASLOT 272
#define AQ    128
#define AT_QO 0
#define AT_KO 16384
#define AT_VH (16384 + 34816)
#define ATTN_SMEM (16384 + 2 * 34816)

__global__ void __launch_bounds__(256, 2) attn_tc_kernel()
{
    extern __shared__ __align__(1024) char smc[];
    uint32_t sb = smem_u32(smc);
    int tid = threadIdx.x;
    int lane = tid & 31, w = tid >> 5;
    int h = blockIdx.x, tile = blockIdx.y;
    int q0 = NP + tile * AQ;
    int kmin = q0 - (WIN - 1);
    int hoff = h * HD;

    // ---- stage Q (128x64) ----
    for (int i = tid; i < 1024; i += 256) {
        int r = i >> 3, c = i & 7;
        uint4 v = *(const uint4*)(g_Qh + (size_t)(q0 + r) * D_MODEL + hoff + c * 8);
        *(uint4*)(smc + AT_QO + r * 128 + ((c * 16) ^ ((r & 7) << 4))) = v;
    }
    // ---- stage K, V (clamp only window slots) ----
    for (int i = tid; i < ASLOT * 8; i += 256) {
        int s = i >> 3, c = i & 7;
        int key = (s < 4) ? s : min(max(kmin + s - 4, NP), T_TOT - 1);
        size_t gidx = (size_t)key * D_MODEL + hoff + c * 8;
        uint32_t off = s * 128 + ((c * 16) ^ ((s & 7) << 4));
        *(uint4*)(smc + AT_KO + off) = *(const uint4*)(g_Kh + gidx);
        *(uint4*)(smc + AT_VH + off) = *(const uint4*)(g_Vh + gidx);
    }
    __syncthreads();

    // ---- per-warp Q fragments (rows 16w..16w+15, k=64) ----
    uint32_t qf[4][4];
    {
        int ar = 16 * w + (lane & 15);
        uint32_t base = sb + AT_QO + ar * 128;
        uint32_t sw = (ar & 7) << 4;
        int ak = (lane >> 4) * 16;
#pragma unroll
        for (int ks = 0; ks < 4; ks++)
            LDSM4(qf[ks][0], qf[ks][1], qf[ks][2], qf[ks][3],
                  base + ((ks * 32 + ak) ^ sw));
    }

    int qrow0 = q0 + 16 * w + (lane >> 2);
    int ccol = (lane & 3) * 2;

    float o[8][4];
#pragma unroll
    for (int n = 0; n < 8; n++)
#pragma unroll
        for (int j = 0; j < 4; j++) o[n][j] = 0.f;
    float l0 = 0.f, l1 = 0.f;

    int krel = (lane & 7) + ((lane >> 4) << 3);
    int kb2 = ((lane >> 3) & 1) * 16;
    int vrel = lane & 15;

    auto process_block = [&](int bi, bool masked) {
        int sbase_slot = bi * 16;
        float s0[4] = {0.f, 0.f, 0.f, 0.f}, s1[4] = {0.f, 0.f, 0.f, 0.f};
        {
            int r = sbase_slot + krel;
            uint32_t base = sb + AT_KO + r * 128;
            uint32_t sw = (r & 7) << 4;
#pragma unroll
            for (int ks = 0; ks < 4; ks++) {
                uint32_t b0, b1, b2, b3;
                LDSM4(b0, b1, b2, b3, base + ((ks * 32 + kb2) ^ sw));
                MMA16816(s0, qf[ks][0], qf[ks][1], qf[ks][2], qf[ks][3], b0, b1);
                MMA16816(s1, qf[ks][0], qf[ks][1], qf[ks][2], qf[ks][3], b2, b3);
            }
        }
        float p[8];
        if (masked) {
#pragma unroll
            for (int e = 0; e < 8; e++) {
                int tilen = e >> 2;
                int j = e & 3;
                int slot = sbase_slot + tilen * 8 + ccol + (j & 1);
                int qr = (j < 2) ? qrow0 : qrow0 + 8;
                float sc = tilen ? s1[j] : s0[j];
                int k = slot < 4 ? slot : kmin + slot - 4;
                bool valid = (slot < 4) | ((k >= NP) & (k <= qr) & (k > qr - WIN));
                p[e] = valid ? __expf(sc * 0.125f) : 0.f;
            }
        } else {
#pragma unroll
            for (int e = 0; e < 8; e++) {
                float sc = (e >> 2) ? s1[e & 3] : s0[e & 3];
                p[e] = __expf(sc * 0.125f);
            }
        }
        l0 += p[0] + p[1] + p[4] + p[5];
        l1 += p[2] + p[3] + p[6] + p[7];
        uint32_t a0 = pack2h(p[0], p[1]);
        uint32_t a1 = pack2h(p[2], p[3]);
        uint32_t a2 = pack2h(p[4], p[5]);
        uint32_t a3 = pack2h(p[6], p[7]);
        {
            int r = sbase_slot + vrel;
            uint32_t swv = (r & 7) << 4;
            uint32_t bh = sb + AT_VH + r * 128;
#pragma unroll
            for (int nt = 0; nt < 8; nt++) {
                uint32_t v0, v1;
                LDSM2T(v0, v1, bh + ((nt * 16) ^ swv));
                MMA16816(o[nt], a0, a1, a2, a3, v0, v1);
            }
        }
    };

    bool safe = (tile >= 1);   // kmin >= NP: interior blocks need no mask
    process_block(0, true);
    if (w >= 1) process_block(w, true);
    process_block(w + 1, true);
    for (int bi = w + 2; bi <= w + 7; bi++) process_block(bi, !safe);
    process_block(w + 8, true);
    process_block(w + 9, true);

    l0 += __shfl_xor_sync(0xffffffffu, l0, 1);
    l0 += __shfl_xor_sync(0xffffffffu, l0, 2);
    l1 += __shfl_xor_sync(0xffffffffu, l1, 1);
    l1 += __shfl_xor_sync(0xffffffffu, l1, 2);
    float inv0 = 1.f / l0, inv1 = 1.f / l1;

    size_t r0 = (size_t)(qrow0 - NP) * D_MODEL + hoff + ccol;
    size_t r1 = r0 + 8 * D_MODEL;
#pragma unroll
    for (int nt = 0; nt < 8; nt++) {
        *(uint32_t*)(&g_at_h[r0 + nt * 8]) = pack2h(o[nt][0] * inv0, o[nt][1] * inv0);
        *(uint32_t*)(&g_at_h[r1 + nt * 8]) = pack2h(o[nt][2] * inv1, o[nt][3] * inv1);
    }
}

// ---------------- launch ----------------
extern "C" void kernel_launch(void* const* d_in, const int* in_sizes, int n_in,
                              void* d_out, int out_size)
{
    (void)in_sizes; (void)n_in; (void)out_size;
    const float* x  = (const float*)d_in[0];
    const float* pm = (const float*)d_in[1];
    const float* Wq = (const float*)d_in[2];
    const float* Wk = (const float*)d_in[3];
    const float* Wv = (const float*)d_in[4];
    const float* Wo = (const float*)d_in[5];
    const float* qw = (const float*)d_in[6];
    const float* qb = (const float*)d_in[7];
    const float* kw = (const float*)d_in[8];
    const float* kb = (const float*)d_in[9];
    const float* vw = (const float*)d_in[10];
    const float* vb = (const float*)d_in[11];
    float* out = (float*)d_out;

    cudaFuncSetAttribute(attn_tc_kernel, cudaFuncAttributeMaxDynamicSharedMemorySize, ATTN_SMEM);
    cudaFuncSetAttribute(gemm_qkv_tc, cudaFuncAttributeMaxDynamicSharedMemorySize, QKV_SMEM);
    cudaFuncSetAttribute(gemm_out_tc, cudaFuncAttributeMaxDynamicSharedMemorySize, OUT_SMEM);

    convert_all_kernel<<<4096 + MPAD, 256>>>(pm, x, Wq, Wk, Wv, Wo);

    gemm_qkv_tc<<<dim3(8, 17, 3), 128, QKV_SMEM>>>();

    conv_silu_norm_kernel<<<dim3(T_TOT / 4, 3), 256>>>(qw, qb, kw, kb, vw, vb);

    attn_tc_kernel<<<dim3(NHEADS, L_SEQ / AQ), 256, ATTN_SMEM>>>();

    gemm_out_tc<<<dim3(8, 16), 128, OUT_SMEM>>>(out);
}

// round 15
// speedup vs baseline: 1.0924x; 1.0663x over previous
#include <cuda_runtime.h>
#include <cuda_fp16.h>
#include <math.h>
#include <stdint.h>

#define D_MODEL 1024
#define T_TOT   2052
#define MPAD    2176   // 17*128
#define L_SEQ   2048
#define NP      4
#define NHEADS  16
#define HD      64
#define WIN     128

// ---------------- scratch (device globals: allocation-free) ----------------
__device__ __half g_QKVh[3][T_TOT * D_MODEL]; // pre-conv Q,K,V (fp16, GEMM out)
__device__ __half g_Qh[T_TOT * D_MODEL];      // post conv+silu+norm, fp16
__device__ __half g_Kh[T_TOT * D_MODEL];
__device__ __half g_Vh[T_TOT * D_MODEL];
__device__ __half g_xp_h[MPAD * D_MODEL];     // input (pm;x) fp16
__device__ __half g_w_h[4][D_MODEL * D_MODEL];// weights fp16
__device__ __half g_at_h[L_SEQ * D_MODEL];    // attention output fp16

// ---------------- helpers ----------------
__device__ __forceinline__ uint32_t smem_u32(const void* p) {
    uint32_t a;
    asm("{ .reg .u64 t; cvta.to.shared.u64 t, %1; cvt.u32.u64 %0, t; }" : "=r"(a) : "l"(p));
    return a;
}

#define LDSM4(R0, R1, R2, R3, ADDR) \
    asm volatile("ldmatrix.sync.aligned.m8n8.x4.shared.b16 {%0,%1,%2,%3}, [%4];" \
                 : "=r"(R0), "=r"(R1), "=r"(R2), "=r"(R3) : "r"(ADDR))

#define LDSM2T(R0, R1, ADDR) \
    asm volatile("ldmatrix.sync.aligned.m8n8.x2.trans.shared.b16 {%0,%1}, [%2];" \
                 : "=r"(R0), "=r"(R1) : "r"(ADDR))

#define MMA16816(D, A0, A1, A2, A3, B0, B1) \
    asm volatile("mma.sync.aligned.m16n8k16.row.col.f32.f16.f16.f32 " \
                 "{%0,%1,%2,%3}, {%4,%5,%6,%7}, {%8,%9}, {%0,%1,%2,%3};" \
                 : "+f"((D)[0]), "+f"((D)[1]), "+f"((D)[2]), "+f"((D)[3]) \
                 : "r"(A0), "r"(A1), "r"(A2), "r"(A3), "r"(B0), "r"(B1))

#define CP_ASYNC16(S, G) \
    asm volatile("cp.async.cg.shared.global [%0], [%1], 16;" :: "r"(S), "l"(G))
#define CP_COMMIT()  asm volatile("cp.async.commit_group;" ::: "memory")

__device__ __forceinline__ uint32_t pack2h(float a, float b) {
    __half2 h = __floats2half2_rn(a, b);
    return *(uint32_t*)&h;
}
__device__ __forceinline__ uint2 cvt4h(float4 v) {
    uint2 r;
    r.x = pack2h(v.x, v.y);
    r.y = pack2h(v.z, v.w);
    return r;
}

// fused converts: blocks [0,4096) = weights, [4096, 4096+2176) = xp
__global__ void __launch_bounds__(256) convert_all_kernel(const float* __restrict__ pm,
                                                          const float* __restrict__ x,
                                                          const float* __restrict__ Wq,
                                                          const float* __restrict__ Wk,
                                                          const float* __restrict__ Wv,
                                                          const float* __restrict__ Wo)
{
    int bx = blockIdx.x;
    if (bx < 4096) {
        int w = bx >> 10;
        const float* src = (w == 0) ? Wq : (w == 1) ? Wk : (w == 2) ? Wv : Wo;
        int i = ((bx & 1023) * 256 + threadIdx.x) * 4;
        *(uint2*)(&g_w_h[w][i]) = cvt4h(*(const float4*)(src + i));
    } else {
        int i = ((bx - 4096) * 256 + threadIdx.x) * 4;
        int row = i >> 10, col = i & 1023;
        float4 v = make_float4(0.f, 0.f, 0.f, 0.f);
        if (row < NP)          v = *(const float4*)(pm + row * D_MODEL + col);
        else if (row < T_TOT)  v = *(const float4*)(x + (size_t)(row - NP) * D_MODEL + col);
        *(uint2*)(&g_xp_h[i]) = cvt4h(v);
    }
}

// ---------------- mma.sync GEMM: C[BM,128]-tile = A @ B^T ----------------
// 4 warps: 2 in M (warp tile BM/2) x 2 in N (warp tile 64). 3-stage cp.async.
// BM=128: stage 32KB (QKV winner, 2 CTAs/SM). BM=64: stage 24KB (out, 3 CTAs/SM).
#define QKV_SMEM (3 * 32768)
#define OUT_SMEM (3 * 24576)

template <int BM, int NSTAGE, typename OutT>
__device__ __forceinline__ void gemm_body(const __half* __restrict__ Ah,
                                          const __half* __restrict__ Bh,
                                          OutT* __restrict__ C, int Mrows)
{
    constexpr int STAGE_BYTES = BM * 128 + 16384;
    constexpr int MI = BM / 32;           // 16-row m-tiles per warp
    constexpr int ACHUNK = BM * 8;        // A 16B-chunks per stage
    extern __shared__ __align__(1024) char sm[];
    uint32_t sbase = smem_u32(sm);
    int tid = threadIdx.x;
    int lane = tid & 31, wid = tid >> 5;
    int bm = blockIdx.y, bn = blockIdx.x;

    const __half* srcA = Ah + (size_t)bm * BM * D_MODEL;
    const __half* srcB = Bh + (size_t)bn * 128 * D_MODEL;

    auto issue_chunk = [&](int kc, int s) {
        uint32_t stage = sbase + s * STAGE_BYTES;
#pragma unroll
        for (int it = 0; it < (ACHUNK + 1024) / 128; it++) {
            int g = it * 128 + tid;
            int mat = g >= ACHUNK;
            int r = mat ? ((g - ACHUNK) >> 3) : (g >> 3);
            int c = g & 7;
            const __half* gp = (mat ? srcB : srcA) + (size_t)r * D_MODEL + kc * 64 + c * 8;
            uint32_t so = stage + mat * (BM * 128) + r * 128 + ((c * 16) ^ ((r & 7) << 4));
            CP_ASYNC16(so, gp);
        }
    };

    int m_base = (wid & 1) * (BM / 2);
    int n_base = (wid >> 1) * 64;

    int arow0 = m_base + (lane & 15);
    int ak2 = ((lane >> 4) * 8) * 2;
    int brow0 = n_base + (lane & 7) + ((lane >> 4) << 3);
    int bk2 = (((lane >> 3) & 1) * 8) * 2;

    uint32_t aoffs[MI], asw[MI], boffs[4], bsw[4];
#pragma unroll
    for (int mi = 0; mi < MI; mi++) {
        int r = arow0 + mi * 16;
        aoffs[mi] = r * 128; asw[mi] = (r & 7) << 4;
    }
#pragma unroll
    for (int p = 0; p < 4; p++) {
        int r = brow0 + p * 16;
        boffs[p] = r * 128; bsw[p] = (r & 7) << 4;
    }

    float acc[MI][8][4];
#pragma unroll
    for (int mi = 0; mi < MI; mi++)
#pragma unroll
        for (int n = 0; n < 8; n++)
#pragma unroll
            for (int j = 0; j < 4; j++) acc[mi][n][j] = 0.f;

#pragma unroll
    for (int s = 0; s < NSTAGE; s++) { issue_chunk(s, s); CP_COMMIT(); }

    for (int kc = 0; kc < 16; kc++) {
        asm volatile("cp.async.wait_group %0;" :: "n"(NSTAGE - 1) : "memory");
        __syncthreads();
        uint32_t stage = sbase + (kc % NSTAGE) * STAGE_BYTES;
        uint32_t AH = stage, BH = stage + BM * 128;
#pragma unroll
        for (int ks = 0; ks < 4; ks++) {
            uint32_t kb2 = ks * 32;
            uint32_t ah[MI][4];
#pragma unroll
            for (int mi = 0; mi < MI; mi++)
                LDSM4(ah[mi][0], ah[mi][1], ah[mi][2], ah[mi][3],
                      AH + aoffs[mi] + ((kb2 + ak2) ^ asw[mi]));
#pragma unroll
            for (int p = 0; p < 4; p++) {
                uint32_t bh[4];
                LDSM4(bh[0], bh[1], bh[2], bh[3], BH + boffs[p] + ((kb2 + bk2) ^ bsw[p]));
#pragma unroll
                for (int mi = 0; mi < MI; mi++) {
                    MMA16816(acc[mi][2 * p],     ah[mi][0], ah[mi][1], ah[mi][2], ah[mi][3], bh[0], bh[1]);
                    MMA16816(acc[mi][2 * p + 1], ah[mi][0], ah[mi][1], ah[mi][2], ah[mi][3], bh[2], bh[3]);
                }
            }
        }
        __syncthreads();
        int cN = kc + NSTAGE;
        if (cN < 16) issue_chunk(cN, cN % NSTAGE);
        CP_COMMIT();
    }

    int crow = lane >> 2;
    int ccol = (lane & 3) * 2;
#pragma unroll
    for (int mi = 0; mi < MI; mi++) {
#pragma unroll
        for (int n = 0; n < 8; n++) {
            int row0 = bm * BM + m_base + mi * 16 + crow;
            int col = bn * 128 + n_base + n * 8 + ccol;
            if (row0 < Mrows) {
                if constexpr (sizeof(OutT) == 2)
                    *(uint32_t*)((__half*)C + (size_t)row0 * D_MODEL + col) = pack2h(acc[mi][n][0], acc[mi][n][1]);
                else
                    *(float2*)((float*)C + (size_t)row0 * D_MODEL + col) = make_float2(acc[mi][n][0], acc[mi][n][1]);
            }
            int row1 = row0 + 8;
            if (row1 < Mrows) {
                if constexpr (sizeof(OutT) == 2)
                    *(uint32_t*)((__half*)C + (size_t)row1 * D_MODEL + col) = pack2h(acc[mi][n][2], acc[mi][n][3]);
                else
                    *(float2*)((float*)C + (size_t)row1 * D_MODEL + col) = make_float2(acc[mi][n][2], acc[mi][n][3]);
            }
        }
    }
}

__global__ void __launch_bounds__(128, 2) gemm_qkv_tc(void)
{
    int z = blockIdx.z;
    gemm_body<128, 3, __half>(g_xp_h, g_w_h[z], g_QKVh[z], T_TOT);
}
__global__ void __launch_bounds__(128, 3) gemm_out_tc(float* __restrict__ out)
{
    gemm_body<64, 3, float>(g_at_h, g_w_h[3], out, L_SEQ);
}

// ---------------- fused conv(k=3) + bias + SiLU + (L2 norm) -> fp16 ----
__global__ void __launch_bounds__(256) conv_silu_norm_kernel(const float* __restrict__ qw,
                                                             const float* __restrict__ qb,
                                                             const float* __restrict__ kw,
                                                             const float* __restrict__ kb,
                                                             const float* __restrict__ vw,
                                                             const float* __restrict__ vb)
{
    int m = blockIdx.y;
    int t0 = blockIdx.x * 4;
    const float* w = (m == 0) ? qw : (m == 1) ? kw : vw;
    const float* b = (m == 0) ? qb : (m == 1) ? kb : vb;
    const __half* X = g_QKVh[m];
    int tid = threadIdx.x;
    int d4 = tid * 4;

    float w0[4], w1[4], w2[4], bb[4];
#pragma unroll
    for (int j = 0; j < 4; j++) {
        w0[j] = w[(d4 + j) * 3 + 0];
        w1[j] = w[(d4 + j) * 3 + 1];
        w2[j] = w[(d4 + j) * 3 + 2];
        bb[j] = b[d4 + j];
    }

    float xr[6][4];
#pragma unroll
    for (int i = 0; i < 6; i++) {
        int t = t0 - 2 + i;
        if (t >= 0) {
            uint2 hv = *(const uint2*)(X + (size_t)t * D_MODEL + d4);
            __half2 h01 = *(__half2*)&hv.x;
            __half2 h23 = *(__half2*)&hv.y;
            xr[i][0] = __low2float(h01); xr[i][1] = __high2float(h01);
            xr[i][2] = __low2float(h23); xr[i][3] = __high2float(h23);
        } else {
            xr[i][0] = xr[i][1] = xr[i][2] = xr[i][3] = 0.f;
        }
    }

    float y[4][4];
    float ss[4] = {0.f, 0.f, 0.f, 0.f};
#pragma unroll
    for (int tt = 0; tt < 4; tt++) {
#pragma unroll
        for (int j = 0; j < 4; j++) {
            float z = w0[j] * xr[tt][j] + w1[j] * xr[tt + 1][j] + w2[j] * xr[tt + 2][j] + bb[j];
            float yv = z / (1.f + __expf(-z));
            y[tt][j] = yv;
            ss[tt] += yv * yv;
        }
    }

    __shared__ float red[4][8];
#pragma unroll
    for (int o = 16; o > 0; o >>= 1) {
#pragma unroll
        for (int tt = 0; tt < 4; tt++) ss[tt] += __shfl_xor_sync(0xffffffffu, ss[tt], o);
    }
    if ((tid & 31) == 0) {
#pragma unroll
        for (int tt = 0; tt < 4; tt++) red[tt][tid >> 5] = ss[tt];
    }
    __syncthreads();
    float inv[4];
#pragma unroll
    for (int tt = 0; tt < 4; tt++) {
        float total = red[tt][0] + red[tt][1] + red[tt][2] + red[tt][3]
                    + red[tt][4] + red[tt][5] + red[tt][6] + red[tt][7];
        inv[tt] = (m < 2) ? 1.f / fmaxf(sqrtf(total), 1e-12f) : 1.f;
    }

    __half* dst = (m == 0) ? g_Qh : (m == 1) ? g_Kh : g_Vh;
#pragma unroll
    for (int tt = 0; tt < 4; tt++) {
        uint2 hv = cvt4h(make_float4(y[tt][0] * inv[tt], y[tt][1] * inv[tt],
                                     y[tt][2] * inv[tt], y[tt][3] * inv[tt]));
        *(uint2*)(dst + (size_t)(t0 + tt) * D_MODEL + d4) = hv;
    }
}

// ---------------- tensor-core attention (AQ=128, 8 warps, 2 CTAs/SM) ------
// Slots: 0-3 persistent, 4..258 window keys [q0-127, q0+127], padded to 272.
// Warp w owns queries 16w..16w+15; needs blocks w..w+9 + block 0.
// Interior blocks w+2..w+7 are provably fully-valid when tile>=1 -> mask-free.
#define ASLOT 272
#define AQ    128
#define AT_QO 0
#define AT_KO 16384
#define AT_VH (16384 + 34816)
#define ATTN_SMEM (16384 + 2 * 34816)

__global__ void __launch_bounds__(256, 2) attn_tc_kernel()
{
    extern __shared__ __align__(1024) char smc[];
    uint32_t sb = smem_u32(smc);
    int tid = threadIdx.x;
    int lane = tid & 31, w = tid >> 5;
    int h = blockIdx.x, tile = blockIdx.y;
    int q0 = NP + tile * AQ;
    int kmin = q0 - (WIN - 1);
    int hoff = h * HD;

    // ---- stage Q (128x64) ----
    for (int i = tid; i < 1024; i += 256) {
        int r = i >> 3, c = i & 7;
        uint4 v = *(const uint4*)(g_Qh + (size_t)(q0 + r) * D_MODEL + hoff + c * 8);
        *(uint4*)(smc + AT_QO + r * 128 + ((c * 16) ^ ((r & 7) << 4))) = v;
    }
    // ---- stage K, V (clamp only window slots) ----
    for (int i = tid; i < ASLOT * 8; i += 256) {
        int s = i >> 3, c = i & 7;
        int key = (s < 4) ? s : min(max(kmin + s - 4, NP), T_TOT - 1);
        size_t gidx = (size_t)key * D_MODEL + hoff + c * 8;
        uint32_t off = s * 128 + ((c * 16) ^ ((s & 7) << 4));
        *(uint4*)(smc + AT_KO + off) = *(const uint4*)(g_Kh + gidx);
        *(uint4*)(smc + AT_VH + off) = *(const uint4*)(g_Vh + gidx);
    }
    __syncthreads();

    // ---- per-warp Q fragments (rows 16w..16w+15, k=64) ----
    uint32_t qf[4][4];
    {
        int ar = 16 * w + (lane & 15);
        uint32_t base = sb + AT_QO + ar * 128;
        uint32_t sw = (ar & 7) << 4;
        int ak = (lane >> 4) * 16;
#pragma unroll
        for (int ks = 0; ks < 4; ks++)
            LDSM4(qf[ks][0], qf[ks][1], qf[ks][2], qf[ks][3],
                  base + ((ks * 32 + ak) ^ sw));
    }

    int qrow0 = q0 + 16 * w + (lane >> 2);
    int ccol = (lane & 3) * 2;

    float o[8][4];
#pragma unroll
    for (int n = 0; n < 8; n++)
#pragma unroll
        for (int j = 0; j < 4; j++) o[n][j] = 0.f;
    float l0 = 0.f, l1 = 0.f;

    int krel = (lane & 7) + ((lane >> 4) << 3);
    int kb2 = ((lane >> 3) & 1) * 16;
    int vrel = lane & 15;

    auto process_block = [&](int bi, bool masked) {
        int sbase_slot = bi * 16;
        float s0[4] = {0.f, 0.f, 0.f, 0.f}, s1[4] = {0.f, 0.f, 0.f, 0.f};
        {
            int r = sbase_slot + krel;
            uint32_t base = sb + AT_KO + r * 128;
            uint32_t sw = (r & 7) << 4;
#pragma unroll
            for (int ks = 0; ks < 4; ks++) {
                uint32_t b0, b1, b2, b3;
                LDSM4(b0, b1, b2, b3, base + ((ks * 32 + kb2) ^ sw));
                MMA16816(s0, qf[ks][0], qf[ks][1], qf[ks][2], qf[ks][3], b0, b1);
                MMA16816(s1, qf[ks][0], qf[ks][1], qf[ks][2], qf[ks][3], b2, b3);
            }
        }
        float p[8];
        if (masked) {
#pragma unroll
            for (int e = 0; e < 8; e++) {
                int tilen = e >> 2;
                int j = e & 3;
                int slot = sbase_slot + tilen * 8 + ccol + (j & 1);
                int qr = (j < 2) ? qrow0 : qrow0 + 8;
                float sc = tilen ? s1[j] : s0[j];
                int k = slot < 4 ? slot : kmin + slot - 4;
                bool valid = (slot < 4) | ((k >= NP) & (k <= qr) & (k > qr - WIN));
                p[e] = valid ? __expf(sc * 0.125f) : 0.f;
            }
        } else {
#pragma unroll
            for (int e = 0; e < 8; e++) {
                float sc = (e >> 2) ? s1[e & 3] : s0[e & 3];
                p[e] = __expf(sc * 0.125f);
            }
        }
        l0 += p[0] + p[1] + p[4] + p[5];
        l1 += p[2] + p[3] + p[6] + p[7];
        uint32_t a0 = pack2h(p[0], p[1]);
        uint32_t a1 = pack2h(p[2], p[3]);
        uint32_t a2 = pack2h(p[4], p[5]);
        uint32_t a3 = pack2h(p[6], p[7]);
        {
            int r = sbase_slot + vrel;
            uint32_t swv = (r & 7) << 4;
            uint32_t bh = sb + AT_VH + r * 128;
#pragma unroll
            for (int nt = 0; nt < 8; nt++) {
                uint32_t v0, v1;
                LDSM2T(v0, v1, bh + ((nt * 16) ^ swv));
                MMA16816(o[nt], a0, a1, a2, a3, v0, v1);
            }
        }
    };

    bool safe = (tile >= 1);   // kmin >= NP: interior blocks need no mask
    process_block(0, true);
    if (w >= 1) process_block(w, true);
    process_block(w + 1, true);
    for (int bi = w + 2; bi <= w + 7; bi++) process_block(bi, !safe);
    process_block(w + 8, true);
    process_block(w + 9, true);

    l0 += __shfl_xor_sync(0xffffffffu, l0, 1);
    l0 += __shfl_xor_sync(0xffffffffu, l0, 2);
    l1 += __shfl_xor_sync(0xffffffffu, l1, 1);
    l1 += __shfl_xor_sync(0xffffffffu, l1, 2);
    float inv0 = 1.f / l0, inv1 = 1.f / l1;

    size_t r0 = (size_t)(qrow0 - NP) * D_MODEL + hoff + ccol;
    size_t r1 = r0 + 8 * D_MODEL;
#pragma unroll
    for (int nt = 0; nt < 8; nt++) {
        *(uint32_t*)(&g_at_h[r0 + nt * 8]) = pack2h(o[nt][0] * inv0, o[nt][1] * inv0);
        *(uint32_t*)(&g_at_h[r1 + nt * 8]) = pack2h(o[nt][2] * inv1, o[nt][3] * inv1);
    }
}

// ---------------- launch ----------------
extern "C" void kernel_launch(void* const* d_in, const int* in_sizes, int n_in,
                              void* d_out, int out_size)
{
    (void)in_sizes; (void)n_in; (void)out_size;
    const float* x  = (const float*)d_in[0];
    const float* pm = (const float*)d_in[1];
    const float* Wq = (const float*)d_in[2];
    const float* Wk = (const float*)d_in[3];
    const float* Wv = (const float*)d_in[4];
    const float* Wo = (const float*)d_in[5];
    const float* qw = (const float*)d_in[6];
    const float* qb = (const float*)d_in[7];
    const float* kw = (const float*)d_in[8];
    const float* kb = (const float*)d_in[9];
    const float* vw = (const float*)d_in[10];
    const float* vb = (const float*)d_in[11];
    float* out = (float*)d_out;

    cudaFuncSetAttribute(attn_tc_kernel, cudaFuncAttributeMaxDynamicSharedMemorySize, ATTN_SMEM);
    cudaFuncSetAttribute(gemm_qkv_tc, cudaFuncAttributeMaxDynamicSharedMemorySize, QKV_SMEM);
    cudaFuncSetAttribute(gemm_out_tc, cudaFuncAttributeMaxDynamicSharedMemorySize, OUT_SMEM);

    convert_all_kernel<<<4096 + MPAD, 256>>>(pm, x, Wq, Wk, Wv, Wo);

    gemm_qkv_tc<<<dim3(8, 17, 3), 128, QKV_SMEM>>>();

    conv_silu_norm_kernel<<<dim3(T_TOT / 4, 3), 256>>>(qw, qb, kw, kb, vw, vb);

    attn_tc_kernel<<<dim3(NHEADS, L_SEQ / AQ), 256, ATTN_SMEM>>>();

    gemm_out_tc<<<dim3(8, 32), 128, OUT_SMEM>>>(out);
}